// round 15
// baseline (speedup 1.0000x reference)
#include <cuda_runtime.h>
#include <cuda_fp16.h>
#include <cstdint>

#define NROWS  131072
#define DDIM   64
#define KCODES 4096
#define MTILE  128
#define NTILE  64
#define NUM_TILES (KCODES / NTILE)   // 64
#define THREADS 256

__device__ float  g_e2[KCODES];
__device__ __half g_ehi[KCODES * DDIM];
__device__ __half g_elo[KCODES * DDIM];

// ---------------- helpers ----------------
static __device__ __forceinline__ uint32_t pack2(__half a, __half b) {
    uint32_t lo = (uint32_t)__half_as_ushort(a);
    uint32_t hi = (uint32_t)__half_as_ushort(b);
    return lo | (hi << 16);
}
static __device__ __forceinline__ uint32_t smem_u32(const void* p) {
    uint32_t a;
    asm("{ .reg .u64 t; cvta.to.shared.u64 t, %1; cvt.u32.u64 %0, t; }" : "=r"(a) : "l"(p));
    return a;
}
static __device__ __forceinline__ uint32_t sw128(uint32_t off) {
    return off ^ ((off >> 3) & 0x70);
}
static __device__ __forceinline__ void ldmx4(uint32_t& r0, uint32_t& r1, uint32_t& r2, uint32_t& r3,
                                             uint32_t addr) {
    asm volatile("ldmatrix.sync.aligned.m8n8.x4.shared.b16 {%0,%1,%2,%3}, [%4];"
                 : "=r"(r0), "=r"(r1), "=r"(r2), "=r"(r3) : "r"(addr));
}
// fp32-accumulator HMMA (hi*hi pass)
static __device__ __forceinline__ void mma16816(float* d, const uint32_t* a, uint32_t b0, uint32_t b1) {
    asm volatile(
        "mma.sync.aligned.m16n8k16.row.col.f32.f16.f16.f32 "
        "{%0,%1,%2,%3}, {%4,%5,%6,%7}, {%8,%9}, {%0,%1,%2,%3};"
        : "+f"(d[0]), "+f"(d[1]), "+f"(d[2]), "+f"(d[3])
        : "r"(a[0]), "r"(a[1]), "r"(a[2]), "r"(a[3]), "r"(b0), "r"(b1));
}
// f16-accumulator HMMA (correction passes; tiny magnitudes)
static __device__ __forceinline__ void mma16816h(uint32_t* d, const uint32_t* a, uint32_t b0, uint32_t b1) {
    asm volatile(
        "mma.sync.aligned.m16n8k16.row.col.f16.f16.f16.f16 "
        "{%0,%1}, {%2,%3,%4,%5}, {%6,%7}, {%0,%1};"
        : "+r"(d[0]), "+r"(d[1])
        : "r"(a[0]), "r"(a[1]), "r"(a[2]), "r"(a[3]), "r"(b0), "r"(b1));
}
static __device__ __forceinline__ void cpasync16(uint32_t dst, const void* src) {
    asm volatile("cp.async.cg.shared.global [%0], [%1], 16;" :: "r"(dst), "l"(src));
}
#define CP_COMMIT() asm volatile("cp.async.commit_group;" ::: "memory")
#define CP_WAIT1()  asm volatile("cp.async.wait_group 1;" ::: "memory")
#define CP_WAIT0()  asm volatile("cp.async.wait_group 0;" ::: "memory")

// top-3 insertion (strict <, earliest index wins ties)
static __device__ __forceinline__ void ins3(float s, int i,
                                            float& b0, int& x0,
                                            float& b1, int& x1,
                                            float& b2, int& x2) {
    if (s < b2) {
        if (s < b1) {
            b2 = b1; x2 = x1;
            if (s < b0) { b1 = b0; x1 = x0; b0 = s; x0 = i; }
            else        { b1 = s;  x1 = i; }
        } else {
            b2 = s; x2 = i;
        }
    }
}

// ---- prep: e2 + fp16 hi/lo split of embed ----
__global__ void prep_kernel(const float* __restrict__ embed) {
    int k = blockIdx.x * blockDim.x + threadIdx.x;
    if (k >= KCODES) return;
    const float4* e = reinterpret_cast<const float4*>(embed + (size_t)k * DDIM);
    uint32_t* hh = reinterpret_cast<uint32_t*>(g_ehi + (size_t)k * DDIM);
    uint32_t* ll = reinterpret_cast<uint32_t*>(g_elo + (size_t)k * DDIM);
    float s = 0.f;
#pragma unroll
    for (int i = 0; i < DDIM / 4; i++) {
        float4 v = e[i];
        s += v.x * v.x + v.y * v.y + v.z * v.z + v.w * v.w;
        __half hx = __float2half_rn(v.x), hy = __float2half_rn(v.y);
        __half hz = __float2half_rn(v.z), hw = __float2half_rn(v.w);
        hh[2 * i]     = pack2(hx, hy);
        hh[2 * i + 1] = pack2(hz, hw);
        ll[2 * i]     = pack2(__float2half_rn(v.x - __half2float(hx)),
                              __float2half_rn(v.y - __half2float(hy)));
        ll[2 * i + 1] = pack2(__float2half_rn(v.z - __half2float(hz)),
                              __float2half_rn(v.w - __half2float(hw)));
    }
    g_e2[k] = s;
}

__global__ void zero_kernel(float* __restrict__ p, int n) {
    int i = blockIdx.x * blockDim.x + threadIdx.x;
    if (i < n) p[i] = 0.0f;
}

// smem layout (bytes from aligned base):
//   A_hi 0..16K, A_lo 16K..32K
//   B buf b at 32768 + b*16384: hi +0 (8K), lo +8192 (8K)
//   e2 buf b at 65536 + b*256
#define OFF_AHI 0u
#define OFF_ALO 16384u
#define OFF_B   32768u
#define OFF_E2  65536u
#define SMEM_BYTES (66048 + 128)

static __device__ __forceinline__ void prefetch_tile(uint32_t sb, int t, int buf, int tid) {
    const __half* srch = g_ehi + (size_t)t * NTILE * DDIM;
    const __half* srcl = g_elo + (size_t)t * NTILE * DDIM;
    uint32_t bh = sb + OFF_B + (uint32_t)buf * 16384u;
    uint32_t bl = bh + 8192u;
#pragma unroll
    for (int j = 0; j < 2; j++) {
        int idx = tid + j * THREADS;       // 0..511
        int n = idx >> 3, kb = idx & 7;
        uint32_t off = sw128((uint32_t)(n * 128 + kb * 16));
        cpasync16(bh + off, srch + n * DDIM + kb * 8);
        cpasync16(bl + off, srcl + n * DDIM + kb * 8);
    }
    if (tid < 16) {
        cpasync16(sb + OFF_E2 + (uint32_t)buf * 256u + (uint32_t)tid * 16u,
                  g_e2 + t * NTILE + tid * 4);
    }
    CP_COMMIT();
}

// exact fp32 score = e2[c] - 2 * dot(x_row, e_c)
static __device__ __forceinline__ float exact_score(const float4* xv,
                                                    const float* __restrict__ embed,
                                                    int cand) {
    const float4* ev = reinterpret_cast<const float4*>(embed + (size_t)cand * DDIM);
    float acc = 0.f;
#pragma unroll
    for (int i = 0; i < DDIM / 4; i++) {
        float4 a = xv[i], b = ev[i];
        acc = fmaf(a.x, b.x, acc);
        acc = fmaf(a.y, b.y, acc);
        acc = fmaf(a.z, b.z, acc);
        acc = fmaf(a.w, b.w, acc);
    }
    return fmaf(-2.0f, acc, g_e2[cand]);
}

__global__ void __launch_bounds__(THREADS)
vq_mma_kernel(const float* __restrict__ x, const float* __restrict__ embed,
              float* __restrict__ out_q, float* __restrict__ out_ind,
              float* __restrict__ out_cs, float* __restrict__ out_es)
{
    extern __shared__ char dsm[];
    uint32_t raw = smem_u32(dsm);
    uint32_t sb = (raw + 127u) & ~127u;
    char* sm = dsm + (sb - raw);

    const int tid  = threadIdx.x;
    const int wid  = tid >> 5;
    const int lane = tid & 31;

    // ---- stage A: load x tile [128 x 64] f32, split to fp16 hi/lo in smem ----
    const float* xt = x + (size_t)blockIdx.x * MTILE * DDIM;
#pragma unroll
    for (int i = 0; i < 8; i++) {
        int f4 = tid + i * THREADS;       // 0..2047
        int row = f4 >> 4, c4 = f4 & 15;
        float4 v = reinterpret_cast<const float4*>(xt)[f4];
        __half hx = __float2half_rn(v.x), hy = __float2half_rn(v.y);
        __half hz = __float2half_rn(v.z), hw = __float2half_rn(v.w);
        uint2 hv, lv;
        hv.x = pack2(hx, hy);
        hv.y = pack2(hz, hw);
        lv.x = pack2(__float2half_rn(v.x - __half2float(hx)),
                     __float2half_rn(v.y - __half2float(hy)));
        lv.y = pack2(__float2half_rn(v.z - __half2float(hz)),
                     __float2half_rn(v.w - __half2float(hw)));
        uint32_t off = sw128((uint32_t)(row * 128 + c4 * 8));
        *reinterpret_cast<uint2*>(sm + OFF_AHI + off) = hv;
        *reinterpret_cast<uint2*>(sm + OFF_ALO + off) = lv;
    }
    prefetch_tile(sb, 0, 0, tid);
    __syncthreads();

    // ---- load A fragments (per warp: rows wid*16 .. +15) ----
    uint32_t a_hi[4][4], a_lo[4][4];
    {
        int arow = wid * 16 + (lane & 15);
        uint32_t kbyte = (uint32_t)((lane >> 4) * 16);
#pragma unroll
        for (int kk = 0; kk < 4; kk++) {
            uint32_t off = sw128((uint32_t)(arow * 128 + kk * 32) + kbyte);
            ldmx4(a_hi[kk][0], a_hi[kk][1], a_hi[kk][2], a_hi[kk][3], sb + OFF_AHI + off);
            ldmx4(a_lo[kk][0], a_lo[kk][1], a_lo[kk][2], a_lo[kk][3], sb + OFF_ALO + off);
        }
    }

    // per-lane top-3 for each of the 2 rows this lane covers
    float r0b0 = 3.4e38f, r0b1 = 3.4e38f, r0b2 = 3.4e38f;
    float r1b0 = 3.4e38f, r1b1 = 3.4e38f, r1b2 = 3.4e38f;
    int   r0x0 = 0, r0x1 = 0, r0x2 = 0;
    int   r1x0 = 0, r1x1 = 0, r1x2 = 0;

    const int bn_local   = ((lane >> 4) << 3) + (lane & 7);
    const uint32_t bkoff = (uint32_t)(((lane >> 3) & 1) * 16);

    for (int t = 0; t < NUM_TILES; t++) {
        const int buf = t & 1;
        if (t + 1 < NUM_TILES) { prefetch_tile(sb, t + 1, 1 - buf, tid); CP_WAIT1(); }
        else                   { CP_WAIT0(); }
        __syncthreads();

        const uint32_t bhb = sb + OFF_B + (uint32_t)buf * 16384u;
        const uint32_t blb = bhb + 8192u;
        const float* e2s = reinterpret_cast<const float*>(sm + OFF_E2 + buf * 256);

        float    d[8][4];      // hi*hi, fp32 accum
        uint32_t dc[8][2];     // xl*eh + xh*el, f16 accum
#pragma unroll
        for (int i = 0; i < 8; i++) {
#pragma unroll
            for (int j = 0; j < 4; j++) d[i][j] = 0.f;
            dc[i][0] = 0u; dc[i][1] = 0u;
        }

        // ILP-restructured: per k-step, load ALL B frags, then issue
        // 8 independent hi-MMAs, then 2x8 correction MMAs (reuse distance 8).
#pragma unroll
        for (int kk = 0; kk < 4; kk++) {
            uint32_t bh[4][4], bl[4][4];
#pragma unroll
            for (int p = 0; p < 4; p++) {
                int n = p * 16 + bn_local;
                uint32_t off = sw128((uint32_t)(n * 128 + kk * 32) + bkoff);
                ldmx4(bh[p][0], bh[p][1], bh[p][2], bh[p][3], bhb + off);
                ldmx4(bl[p][0], bl[p][1], bl[p][2], bl[p][3], blb + off);
            }
#pragma unroll
            for (int p = 0; p < 4; p++) {
                mma16816(d[2 * p],     a_hi[kk], bh[p][0], bh[p][1]);
                mma16816(d[2 * p + 1], a_hi[kk], bh[p][2], bh[p][3]);
            }
#pragma unroll
            for (int p = 0; p < 4; p++) {
                mma16816h(dc[2 * p],     a_lo[kk], bh[p][0], bh[p][1]);
                mma16816h(dc[2 * p + 1], a_lo[kk], bh[p][2], bh[p][3]);
            }
#pragma unroll
            for (int p = 0; p < 4; p++) {
                mma16816h(dc[2 * p],     a_hi[kk], bl[p][0], bl[p][1]);
                mma16816h(dc[2 * p + 1], a_hi[kk], bl[p][2], bl[p][3]);
            }
        }
        __syncthreads();

        const int c2 = 2 * (lane & 3);
#pragma unroll
        for (int nf = 0; nf < 8; nf++) {
            int col = nf * 8 + c2;
            float ea = e2s[col], eb = e2s[col + 1];
            int gidx = t * NTILE + col;
            float2 cl = __half22float2(*reinterpret_cast<const __half2*>(&dc[nf][0]));
            float2 ch = __half22float2(*reinterpret_cast<const __half2*>(&dc[nf][1]));
            float s0 = fmaf(-2.f, d[nf][0] + cl.x, ea);
            float s1 = fmaf(-2.f, d[nf][1] + cl.y, eb);
            float s2 = fmaf(-2.f, d[nf][2] + ch.x, ea);
            float s3 = fmaf(-2.f, d[nf][3] + ch.y, eb);
            ins3(s0, gidx,     r0b0, r0x0, r0b1, r0x1, r0b2, r0x2);
            ins3(s1, gidx + 1, r0b0, r0x0, r0b1, r0x1, r0b2, r0x2);
            ins3(s2, gidx,     r1b0, r1x0, r1b1, r1x1, r1b2, r1x2);
            ins3(s3, gidx + 1, r1b0, r1x0, r1b1, r1x1, r1b2, r1x2);
        }
    }

    // ---- exact fp32 recheck of per-lane top-3, then quad reduce ----
    const int g = lane >> 2, c = lane & 3;
    const int row0 = blockIdx.x * MTILE + wid * 16 + g;
    const int row1 = row0 + 8;

    float best0, best1;
    int   bidx0, bidx1;
    {
        float4 xv0[DDIM / 4];
        const float4* xp0 = reinterpret_cast<const float4*>(x + (size_t)row0 * DDIM);
#pragma unroll
        for (int i = 0; i < DDIM / 4; i++) xv0[i] = xp0[i];
        best0 = exact_score(xv0, embed, r0x0); bidx0 = r0x0;
        {
            float s = exact_score(xv0, embed, r0x1);
            if (s < best0 || (s == best0 && r0x1 < bidx0)) { best0 = s; bidx0 = r0x1; }
            s = exact_score(xv0, embed, r0x2);
            if (s < best0 || (s == best0 && r0x2 < bidx0)) { best0 = s; bidx0 = r0x2; }
        }

        float4 xv1[DDIM / 4];
        const float4* xp1 = reinterpret_cast<const float4*>(x + (size_t)row1 * DDIM);
#pragma unroll
        for (int i = 0; i < DDIM / 4; i++) xv1[i] = xp1[i];
        best1 = exact_score(xv1, embed, r1x0); bidx1 = r1x0;
        {
            float s = exact_score(xv1, embed, r1x1);
            if (s < best1 || (s == best1 && r1x1 < bidx1)) { best1 = s; bidx1 = r1x1; }
            s = exact_score(xv1, embed, r1x2);
            if (s < best1 || (s == best1 && r1x2 < bidx1)) { best1 = s; bidx1 = r1x2; }
        }
    }

#pragma unroll
    for (int m = 1; m <= 2; m <<= 1) {
        float os = __shfl_xor_sync(0xFFFFFFFF, best0, m);
        int   oi = __shfl_xor_sync(0xFFFFFFFF, bidx0, m);
        if (os < best0 || (os == best0 && oi < bidx0)) { best0 = os; bidx0 = oi; }
        os = __shfl_xor_sync(0xFFFFFFFF, best1, m);
        oi = __shfl_xor_sync(0xFFFFFFFF, bidx1, m);
        if (os < best1 || (os == best1 && oi < bidx1)) { best1 = os; bidx1 = oi; }
    }

    // ---- per-row outputs ----
    if (c == 0) {
        out_ind[row0] = (float)bidx0;
        out_ind[row1] = (float)bidx1;
        atomicAdd(&out_cs[bidx0], 1.0f);
        atomicAdd(&out_cs[bidx1], 1.0f);
    }
    {
        const float4* eq0 = reinterpret_cast<const float4*>(embed + (size_t)bidx0 * DDIM);
        const float4* eq1 = reinterpret_cast<const float4*>(embed + (size_t)bidx1 * DDIM);
        float4* oq0 = reinterpret_cast<float4*>(out_q + (size_t)row0 * DDIM);
        float4* oq1 = reinterpret_cast<float4*>(out_q + (size_t)row1 * DDIM);
        const float4* xr0 = reinterpret_cast<const float4*>(x + (size_t)row0 * DDIM);
        const float4* xr1 = reinterpret_cast<const float4*>(x + (size_t)row1 * DDIM);
        float* es0 = out_es + (size_t)bidx0 * DDIM;
        float* es1 = out_es + (size_t)bidx1 * DDIM;
#pragma unroll
        for (int i = 0; i < 4; i++) {
            int q = c * 4 + i;
            oq0[q] = eq0[q];
            oq1[q] = eq1[q];
            float4 v0 = xr0[q], v1 = xr1[q];
            atomicAdd(&es0[q * 4 + 0], v0.x); atomicAdd(&es0[q * 4 + 1], v0.y);
            atomicAdd(&es0[q * 4 + 2], v0.z); atomicAdd(&es0[q * 4 + 3], v0.w);
            atomicAdd(&es1[q * 4 + 0], v1.x); atomicAdd(&es1[q * 4 + 1], v1.y);
            atomicAdd(&es1[q * 4 + 2], v1.z); atomicAdd(&es1[q * 4 + 3], v1.w);
        }
    }
}

extern "C" void kernel_launch(void* const* d_in, const int* in_sizes, int n_in,
                              void* d_out, int out_size) {
    const float* x     = (const float*)d_in[0];  // [N, D]
    const float* embed = (const float*)d_in[1];  // [K, D]
    float* out = (float*)d_out;

    float* out_q   = out;                         // N*D
    float* out_ind = out + (size_t)NROWS * DDIM;  // N
    float* out_cs  = out_ind + NROWS;             // K
    float* out_es  = out_cs + KCODES;             // K*D

    const int zn = KCODES + KCODES * DDIM;
    zero_kernel<<<(zn + 255) / 256, 256>>>(out_cs, zn);
    prep_kernel<<<(KCODES + 127) / 128, 128>>>(embed);

    cudaFuncSetAttribute(vq_mma_kernel, cudaFuncAttributeMaxDynamicSharedMemorySize, SMEM_BYTES);
    vq_mma_kernel<<<NROWS / MTILE, THREADS, SMEM_BYTES>>>(x, embed, out_q, out_ind, out_cs, out_es);
}

// round 16
// speedup vs baseline: 1.4778x; 1.4778x over previous
#include <cuda_runtime.h>
#include <cuda_fp16.h>
#include <cstdint>

#define NROWS  131072
#define DDIM   64
#define KCODES 4096
#define MTILE  128
#define NTILE  64
#define NUM_TILES (KCODES / NTILE)   // 64
#define THREADS 256

__device__ float  g_e2[KCODES];
__device__ __half g_ehi[KCODES * DDIM];
__device__ __half g_elo[KCODES * DDIM];

// ---------------- helpers ----------------
static __device__ __forceinline__ uint32_t pack2(__half a, __half b) {
    uint32_t lo = (uint32_t)__half_as_ushort(a);
    uint32_t hi = (uint32_t)__half_as_ushort(b);
    return lo | (hi << 16);
}
static __device__ __forceinline__ uint32_t smem_u32(const void* p) {
    uint32_t a;
    asm("{ .reg .u64 t; cvta.to.shared.u64 t, %1; cvt.u32.u64 %0, t; }" : "=r"(a) : "l"(p));
    return a;
}
static __device__ __forceinline__ uint32_t sw128(uint32_t off) {
    return off ^ ((off >> 3) & 0x70);
}
static __device__ __forceinline__ void ldmx4(uint32_t& r0, uint32_t& r1, uint32_t& r2, uint32_t& r3,
                                             uint32_t addr) {
    asm volatile("ldmatrix.sync.aligned.m8n8.x4.shared.b16 {%0,%1,%2,%3}, [%4];"
                 : "=r"(r0), "=r"(r1), "=r"(r2), "=r"(r3) : "r"(addr));
}
static __device__ __forceinline__ void mma16816(float* d, const uint32_t* a, uint32_t b0, uint32_t b1) {
    asm volatile(
        "mma.sync.aligned.m16n8k16.row.col.f32.f16.f16.f32 "
        "{%0,%1,%2,%3}, {%4,%5,%6,%7}, {%8,%9}, {%0,%1,%2,%3};"
        : "+f"(d[0]), "+f"(d[1]), "+f"(d[2]), "+f"(d[3])
        : "r"(a[0]), "r"(a[1]), "r"(a[2]), "r"(a[3]), "r"(b0), "r"(b1));
}
static __device__ __forceinline__ void cpasync16(uint32_t dst, const void* src) {
    asm volatile("cp.async.cg.shared.global [%0], [%1], 16;" :: "r"(dst), "l"(src));
}
#define CP_COMMIT() asm volatile("cp.async.commit_group;" ::: "memory")
#define CP_WAIT1()  asm volatile("cp.async.wait_group 1;" ::: "memory")
#define CP_WAIT0()  asm volatile("cp.async.wait_group 0;" ::: "memory")

// top-3 insertion (strict <, earliest index wins ties)
static __device__ __forceinline__ void ins3(float s, int i,
                                            float& b0, int& x0,
                                            float& b1, int& x1,
                                            float& b2, int& x2) {
    if (s < b2) {
        if (s < b1) {
            b2 = b1; x2 = x1;
            if (s < b0) { b1 = b0; x1 = x0; b0 = s; x0 = i; }
            else        { b1 = s;  x1 = i; }
        } else {
            b2 = s; x2 = i;
        }
    }
}

// ---- prep: e2 + fp16 hi/lo split of embed ----
__global__ void prep_kernel(const float* __restrict__ embed) {
    int k = blockIdx.x * blockDim.x + threadIdx.x;
    if (k >= KCODES) return;
    const float4* e = reinterpret_cast<const float4*>(embed + (size_t)k * DDIM);
    uint32_t* hh = reinterpret_cast<uint32_t*>(g_ehi + (size_t)k * DDIM);
    uint32_t* ll = reinterpret_cast<uint32_t*>(g_elo + (size_t)k * DDIM);
    float s = 0.f;
#pragma unroll
    for (int i = 0; i < DDIM / 4; i++) {
        float4 v = e[i];
        s += v.x * v.x + v.y * v.y + v.z * v.z + v.w * v.w;
        __half hx = __float2half_rn(v.x), hy = __float2half_rn(v.y);
        __half hz = __float2half_rn(v.z), hw = __float2half_rn(v.w);
        hh[2 * i]     = pack2(hx, hy);
        hh[2 * i + 1] = pack2(hz, hw);
        ll[2 * i]     = pack2(__float2half_rn(v.x - __half2float(hx)),
                              __float2half_rn(v.y - __half2float(hy)));
        ll[2 * i + 1] = pack2(__float2half_rn(v.z - __half2float(hz)),
                              __float2half_rn(v.w - __half2float(hw)));
    }
    g_e2[k] = s;
}

__global__ void zero_kernel(float* __restrict__ p, int n) {
    int i = blockIdx.x * blockDim.x + threadIdx.x;
    if (i < n) p[i] = 0.0f;
}

// smem layout (bytes from aligned base):
//   A_hi 0..16K, A_lo 16K..32K
//   B buf b at 32768 + b*16384: hi +0 (8K), lo +8192 (8K)
//   e2 buf b at 65536 + b*256
#define OFF_AHI 0u
#define OFF_ALO 16384u
#define OFF_B   32768u
#define OFF_E2  65536u
#define SMEM_BYTES (66048 + 128)

static __device__ __forceinline__ void prefetch_tile(uint32_t sb, int t, int buf, int tid) {
    const __half* srch = g_ehi + (size_t)t * NTILE * DDIM;
    const __half* srcl = g_elo + (size_t)t * NTILE * DDIM;
    uint32_t bh = sb + OFF_B + (uint32_t)buf * 16384u;
    uint32_t bl = bh + 8192u;
#pragma unroll
    for (int j = 0; j < 2; j++) {
        int idx = tid + j * THREADS;       // 0..511
        int n = idx >> 3, kb = idx & 7;
        uint32_t off = sw128((uint32_t)(n * 128 + kb * 16));
        cpasync16(bh + off, srch + n * DDIM + kb * 8);
        cpasync16(bl + off, srcl + n * DDIM + kb * 8);
    }
    if (tid < 16) {
        cpasync16(sb + OFF_E2 + (uint32_t)buf * 256u + (uint32_t)tid * 16u,
                  g_e2 + t * NTILE + tid * 4);
    }
    CP_COMMIT();
}

// exact fp32 score = e2[c] - 2 * dot(x_row, e_c)
static __device__ __forceinline__ float exact_score(const float4* xv,
                                                    const float* __restrict__ embed,
                                                    int cand) {
    const float4* ev = reinterpret_cast<const float4*>(embed + (size_t)cand * DDIM);
    float acc = 0.f;
#pragma unroll
    for (int i = 0; i < DDIM / 4; i++) {
        float4 a = xv[i], b = ev[i];
        acc = fmaf(a.x, b.x, acc);
        acc = fmaf(a.y, b.y, acc);
        acc = fmaf(a.z, b.z, acc);
        acc = fmaf(a.w, b.w, acc);
    }
    return fmaf(-2.0f, acc, g_e2[cand]);
}

__global__ void __launch_bounds__(THREADS, 2)
vq_mma_kernel(const float* __restrict__ x, const float* __restrict__ embed,
              float* __restrict__ out_q, float* __restrict__ out_ind,
              float* __restrict__ out_cs, float* __restrict__ out_es)
{
    extern __shared__ char dsm[];
    uint32_t raw = smem_u32(dsm);
    uint32_t sb = (raw + 127u) & ~127u;
    char* sm = dsm + (sb - raw);

    const int tid  = threadIdx.x;
    const int wid  = tid >> 5;
    const int lane = tid & 31;

    // ---- stage A: load x tile [128 x 64] f32, split to fp16 hi/lo in smem ----
    const float* xt = x + (size_t)blockIdx.x * MTILE * DDIM;
#pragma unroll
    for (int i = 0; i < 8; i++) {
        int f4 = tid + i * THREADS;       // 0..2047
        int row = f4 >> 4, c4 = f4 & 15;
        float4 v = reinterpret_cast<const float4*>(xt)[f4];
        __half hx = __float2half_rn(v.x), hy = __float2half_rn(v.y);
        __half hz = __float2half_rn(v.z), hw = __float2half_rn(v.w);
        uint2 hv, lv;
        hv.x = pack2(hx, hy);
        hv.y = pack2(hz, hw);
        lv.x = pack2(__float2half_rn(v.x - __half2float(hx)),
                     __float2half_rn(v.y - __half2float(hy)));
        lv.y = pack2(__float2half_rn(v.z - __half2float(hz)),
                     __float2half_rn(v.w - __half2float(hw)));
        uint32_t off = sw128((uint32_t)(row * 128 + c4 * 8));
        *reinterpret_cast<uint2*>(sm + OFF_AHI + off) = hv;
        *reinterpret_cast<uint2*>(sm + OFF_ALO + off) = lv;
    }
    prefetch_tile(sb, 0, 0, tid);
    __syncthreads();

    // ---- load A_hi fragments only (per warp: rows wid*16 .. +15); A_lo re-read per tile ----
    uint32_t a_hi[4][4];
    uint32_t a_lo_addr[4];
    {
        int arow = wid * 16 + (lane & 15);
        uint32_t kbyte = (uint32_t)((lane >> 4) * 16);
#pragma unroll
        for (int kk = 0; kk < 4; kk++) {
            uint32_t off = sw128((uint32_t)(arow * 128 + kk * 32) + kbyte);
            ldmx4(a_hi[kk][0], a_hi[kk][1], a_hi[kk][2], a_hi[kk][3], sb + OFF_AHI + off);
            a_lo_addr[kk] = sb + OFF_ALO + off;
        }
    }

    // per-lane top-3 for each of the 2 rows this lane covers
    float r0b0 = 3.4e38f, r0b1 = 3.4e38f, r0b2 = 3.4e38f;
    float r1b0 = 3.4e38f, r1b1 = 3.4e38f, r1b2 = 3.4e38f;
    int   r0x0 = 0, r0x1 = 0, r0x2 = 0;
    int   r1x0 = 0, r1x1 = 0, r1x2 = 0;

    const int bn_local   = ((lane >> 4) << 3) + (lane & 7);
    const uint32_t bkoff = (uint32_t)(((lane >> 3) & 1) * 16);

    for (int t = 0; t < NUM_TILES; t++) {
        const int buf = t & 1;
        if (t + 1 < NUM_TILES) { prefetch_tile(sb, t + 1, 1 - buf, tid); CP_WAIT1(); }
        else                   { CP_WAIT0(); }
        __syncthreads();

        const uint32_t bhb = sb + OFF_B + (uint32_t)buf * 16384u;
        const uint32_t blb = bhb + 8192u;
        const float* e2s = reinterpret_cast<const float*>(sm + OFF_E2 + buf * 256);

        float d[8][4];
#pragma unroll
        for (int i = 0; i < 8; i++)
#pragma unroll
            for (int j = 0; j < 4; j++) d[i][j] = 0.f;

#pragma unroll
        for (int kk = 0; kk < 4; kk++) {
            uint32_t al0, al1, al2, al3;
            ldmx4(al0, al1, al2, al3, a_lo_addr[kk]);
            uint32_t a_lo_t[4] = {al0, al1, al2, al3};
#pragma unroll
            for (int p = 0; p < 4; p++) {
                int n = p * 16 + bn_local;
                uint32_t off = sw128((uint32_t)(n * 128 + kk * 32) + bkoff);
                uint32_t h0, h1, h2, h3, l0, l1, l2, l3;
                ldmx4(h0, h1, h2, h3, bhb + off);
                ldmx4(l0, l1, l2, l3, blb + off);
                mma16816(d[2 * p],     a_hi[kk], h0, h1);
                mma16816(d[2 * p],     a_lo_t,   h0, h1);
                mma16816(d[2 * p],     a_hi[kk], l0, l1);
                mma16816(d[2 * p + 1], a_hi[kk], h2, h3);
                mma16816(d[2 * p + 1], a_lo_t,   h2, h3);
                mma16816(d[2 * p + 1], a_hi[kk], l2, l3);
            }
        }
        __syncthreads();

        const int c2 = 2 * (lane & 3);
#pragma unroll
        for (int nf = 0; nf < 8; nf++) {
            int col = nf * 8 + c2;
            float ea = e2s[col], eb = e2s[col + 1];
            int gidx = t * NTILE + col;
            float s0 = fmaf(-2.f, d[nf][0], ea);
            float s1 = fmaf(-2.f, d[nf][1], eb);
            float s2 = fmaf(-2.f, d[nf][2], ea);
            float s3 = fmaf(-2.f, d[nf][3], eb);
            ins3(s0, gidx,     r0b0, r0x0, r0b1, r0x1, r0b2, r0x2);
            ins3(s1, gidx + 1, r0b0, r0x0, r0b1, r0x1, r0b2, r0x2);
            ins3(s2, gidx,     r1b0, r1x0, r1b1, r1x1, r1b2, r1x2);
            ins3(s3, gidx + 1, r1b0, r1x0, r1b1, r1x1, r1b2, r1x2);
        }
    }

    // ---- exact fp32 recheck of per-lane top-3, then quad reduce ----
    const int g = lane >> 2, c = lane & 3;
    const int row0 = blockIdx.x * MTILE + wid * 16 + g;
    const int row1 = row0 + 8;

    float best0, best1;
    int   bidx0, bidx1;
    {
        float4 xv0[DDIM / 4];
        const float4* xp0 = reinterpret_cast<const float4*>(x + (size_t)row0 * DDIM);
#pragma unroll
        for (int i = 0; i < DDIM / 4; i++) xv0[i] = xp0[i];
        best0 = exact_score(xv0, embed, r0x0); bidx0 = r0x0;
        {
            float s = exact_score(xv0, embed, r0x1);
            if (s < best0 || (s == best0 && r0x1 < bidx0)) { best0 = s; bidx0 = r0x1; }
            s = exact_score(xv0, embed, r0x2);
            if (s < best0 || (s == best0 && r0x2 < bidx0)) { best0 = s; bidx0 = r0x2; }
        }

        float4 xv1[DDIM / 4];
        const float4* xp1 = reinterpret_cast<const float4*>(x + (size_t)row1 * DDIM);
#pragma unroll
        for (int i = 0; i < DDIM / 4; i++) xv1[i] = xp1[i];
        best1 = exact_score(xv1, embed, r1x0); bidx1 = r1x0;
        {
            float s = exact_score(xv1, embed, r1x1);
            if (s < best1 || (s == best1 && r1x1 < bidx1)) { best1 = s; bidx1 = r1x1; }
            s = exact_score(xv1, embed, r1x2);
            if (s < best1 || (s == best1 && r1x2 < bidx1)) { best1 = s; bidx1 = r1x2; }
        }
    }

#pragma unroll
    for (int m = 1; m <= 2; m <<= 1) {
        float os = __shfl_xor_sync(0xFFFFFFFF, best0, m);
        int   oi = __shfl_xor_sync(0xFFFFFFFF, bidx0, m);
        if (os < best0 || (os == best0 && oi < bidx0)) { best0 = os; bidx0 = oi; }
        os = __shfl_xor_sync(0xFFFFFFFF, best1, m);
        oi = __shfl_xor_sync(0xFFFFFFFF, bidx1, m);
        if (os < best1 || (os == best1 && oi < bidx1)) { best1 = os; bidx1 = oi; }
    }

    // ---- per-row outputs ----
    if (c == 0) {
        out_ind[row0] = (float)bidx0;
        out_ind[row1] = (float)bidx1;
        atomicAdd(&out_cs[bidx0], 1.0f);
        atomicAdd(&out_cs[bidx1], 1.0f);
    }
    {
        const float4* eq0 = reinterpret_cast<const float4*>(embed + (size_t)bidx0 * DDIM);
        const float4* eq1 = reinterpret_cast<const float4*>(embed + (size_t)bidx1 * DDIM);
        float4* oq0 = reinterpret_cast<float4*>(out_q + (size_t)row0 * DDIM);
        float4* oq1 = reinterpret_cast<float4*>(out_q + (size_t)row1 * DDIM);
        const float4* xr0 = reinterpret_cast<const float4*>(x + (size_t)row0 * DDIM);
        const float4* xr1 = reinterpret_cast<const float4*>(x + (size_t)row1 * DDIM);
        float* es0 = out_es + (size_t)bidx0 * DDIM;
        float* es1 = out_es + (size_t)bidx1 * DDIM;
#pragma unroll
        for (int i = 0; i < 4; i++) {
            int q = c * 4 + i;
            oq0[q] = eq0[q];
            oq1[q] = eq1[q];
            float4 v0 = xr0[q], v1 = xr1[q];
            atomicAdd(&es0[q * 4 + 0], v0.x); atomicAdd(&es0[q * 4 + 1], v0.y);
            atomicAdd(&es0[q * 4 + 2], v0.z); atomicAdd(&es0[q * 4 + 3], v0.w);
            atomicAdd(&es1[q * 4 + 0], v1.x); atomicAdd(&es1[q * 4 + 1], v1.y);
            atomicAdd(&es1[q * 4 + 2], v1.z); atomicAdd(&es1[q * 4 + 3], v1.w);
        }
    }
}

extern "C" void kernel_launch(void* const* d_in, const int* in_sizes, int n_in,
                              void* d_out, int out_size) {
    const float* x     = (const float*)d_in[0];  // [N, D]
    const float* embed = (const float*)d_in[1];  // [K, D]
    float* out = (float*)d_out;

    float* out_q   = out;                         // N*D
    float* out_ind = out + (size_t)NROWS * DDIM;  // N
    float* out_cs  = out_ind + NROWS;             // K
    float* out_es  = out_cs + KCODES;             // K*D

    const int zn = KCODES + KCODES * DDIM;
    zero_kernel<<<(zn + 255) / 256, 256>>>(out_cs, zn);
    prep_kernel<<<(KCODES + 127) / 128, 128>>>(embed);

    cudaFuncSetAttribute(vq_mma_kernel, cudaFuncAttributeMaxDynamicSharedMemorySize, SMEM_BYTES);
    vq_mma_kernel<<<NROWS / MTILE, THREADS, SMEM_BYTES>>>(x, embed, out_q, out_ind, out_cs, out_es);
}